// round 7
// baseline (speedup 1.0000x reference)
#include <cuda_runtime.h>
#include <cuda_bf16.h>
#include <cstdint>

#define N_NODES  50000
#define N_EDGES  800000
#define N_GRAPHS 1024
#define N_PAIRS  16384
#define N_CL     16
#define IN_CH    64
#define EMB      128
#define HID      256

#define SCAN_BLOCKS ((N_NODES + 255) / 256)   // 196

// ---------------- scratch (device globals; no allocations) ----------------
__device__ float g_bufHW[N_NODES * EMB];
__device__ float g_bufAGG[N_NODES * EMB];
__device__ int   g_indeg[N_NODES];
__device__ float g_dinv[N_NODES];
__device__ int   g_rowptr[N_NODES + 1];
__device__ int   g_cursor2[N_NODES];
__device__ int   g_bsum[256];
__device__ int   g_csr_src[N_EDGES];
__device__ float g_csr_nrm[N_EDGES];
__device__ float g_gsum[N_GRAPHS * EMB];
__device__ float g_cnt[N_GRAPHS];
__device__ float g_cntinv[N_GRAPHS];
__device__ int   g_clcnt[N_CL];
__device__ int   g_offs[N_CL + 1];
__device__ int   g_sorted[N_PAIRS];

// ---------------- f32x2 helpers ----------------
__device__ __forceinline__ void fma2(unsigned long long& d,
                                     unsigned long long a, unsigned long long b) {
    asm("fma.rn.f32x2 %0, %1, %2, %0;" : "+l"(d) : "l"(a), "l"(b));
}
__device__ __forceinline__ unsigned long long pack2(float lo, float hi) {
    unsigned long long d;
    asm("mov.b64 %0, {%1, %2};" : "=l"(d) : "f"(lo), "f"(hi));
    return d;
}
__device__ __forceinline__ float2 unpack2(unsigned long long v) {
    float lo, hi;
    asm("mov.b64 {%0, %1}, %2;" : "=f"(lo), "=f"(hi) : "l"(v));
    return make_float2(lo, hi);
}
__device__ __forceinline__ void lds_2x64(unsigned addr,
                                         unsigned long long& a, unsigned long long& b) {
    asm volatile("ld.shared.v2.b64 {%0, %1}, [%2];" : "=l"(a), "=l"(b) : "r"(addr));
}

// ---------------- init ----------------
__global__ void init_kernel() {
    int i = blockIdx.x * blockDim.x + threadIdx.x;
    if (i < N_GRAPHS * EMB) g_gsum[i] = 0.f;
    if (i < N_NODES)  g_indeg[i] = 0;
    if (i < N_GRAPHS) g_cnt[i] = 0.f;
}

// ---------------- degree ----------------
__global__ void degree_kernel(const int* __restrict__ ei) {
    int e = blockIdx.x * blockDim.x + threadIdx.x;
    if (e < N_EDGES) atomicAdd(&g_indeg[ei[N_EDGES + e]], 1);  // target = col
}

// ---------------- CSR build ----------------
__global__ void scanA() {
    __shared__ int s[256];
    int t = threadIdx.x;
    int i = blockIdx.x * 256 + t;
    int v = (i < N_NODES) ? g_indeg[i] : 0;
    s[t] = v; __syncthreads();
#pragma unroll
    for (int off = 1; off < 256; off <<= 1) {
        int x = (t >= off) ? s[t - off] : 0;
        __syncthreads();
        s[t] += x;
        __syncthreads();
    }
    if (i < N_NODES) {
        g_rowptr[i] = s[t] - v;              // block-local exclusive
        g_dinv[i] = rsqrtf((float)(v + 1));  // +1 self-loop
    }
    if (t == 255) g_bsum[blockIdx.x] = s[255];
}

// fused: each block computes its own prefix over g_bsum, applies, writes cursor
__global__ void scanC() {
    __shared__ int warpsum[8];
    __shared__ int boff;
    int t = threadIdx.x, b = blockIdx.x;
    int v = 0;
    for (int j = t; j < b; j += 256) v += g_bsum[j];
#pragma unroll
    for (int off = 16; off; off >>= 1) v += __shfl_down_sync(0xffffffffu, v, off);
    if ((t & 31) == 0) warpsum[t >> 5] = v;
    __syncthreads();
    if (t == 0) {
        int s = 0;
#pragma unroll
        for (int w = 0; w < 8; w++) s += warpsum[w];
        boff = s;
    }
    __syncthreads();
    int i = b * 256 + t;
    if (i < N_NODES) {
        int r = g_rowptr[i] + boff;
        g_rowptr[i] = r;
        g_cursor2[i] = r;
    }
    if (i == 0) g_rowptr[N_NODES] = N_EDGES;
}

__global__ void csr_scatter(const int* __restrict__ ei) {
    int e = blockIdx.x * blockDim.x + threadIdx.x;
    if (e >= N_EDGES) return;
    int r = ei[e];
    int c = ei[N_EDGES + e];
    int pos = atomicAdd(&g_cursor2[c], 1);
    g_csr_src[pos] = r;
    g_csr_nrm[pos] = g_dinv[r] * g_dinv[c];
}

// ---------------- fused pair counting sort (single block) ----------------
__global__ void cl_sort(const int* __restrict__ ecl) {
    __shared__ int hist[N_CL], offs[N_CL], cur[N_CL];
    int tid = threadIdx.x, lane = tid & 31;
    if (tid < N_CL) hist[tid] = 0;
    __syncthreads();
    for (int p = tid; p < N_PAIRS; p += 256) {
        int c = ecl[p];
        unsigned m = __match_any_sync(0xffffffffu, c);
        if (lane == (__ffs(m) - 1)) atomicAdd(&hist[c], __popc(m));
    }
    __syncthreads();
    if (tid == 0) {
        int s = 0;
        for (int c = 0; c < N_CL; c++) { offs[c] = s; cur[c] = s; s += hist[c]; }
    }
    __syncthreads();
    for (int p = tid; p < N_PAIRS; p += 256) {
        int c = ecl[p];
        unsigned m = __match_any_sync(0xffffffffu, c);
        int leader = __ffs(m) - 1;
        int base;
        if (lane == leader) base = atomicAdd(&cur[c], __popc(m));
        base = __shfl_sync(0xffffffffu, base, leader);
        int rank = __popc(m & ((1u << lane) - 1));
        g_sorted[base + rank] = p;
    }
    if (tid < N_CL) { g_clcnt[tid] = hist[tid]; g_offs[tid] = offs[tid]; }
    if (tid == 0) g_offs[N_CL] = N_PAIRS;
}

// ---------------- CSR gather aggregation, unroll 4 ----------------
template <int C>
__global__ void agg_gather(const float* __restrict__ X, float* __restrict__ Y) {
    int w = (blockIdx.x * blockDim.x + threadIdx.x) >> 5;
    if (w >= N_NODES) return;
    int lane = threadIdx.x & 31;
    constexpr int V = C / 32;

    float d = g_dinv[w];
    float sn = d * d;
    float acc[V];
    const float* xp = X + (long)w * C + lane * V;
    if constexpr (V == 4) {
        float4 a = *(const float4*)xp;
        acc[0] = sn * a.x; acc[1] = sn * a.y; acc[2] = sn * a.z; acc[3] = sn * a.w;
    } else {
        float2 a = *(const float2*)xp;
        acc[0] = sn * a.x; acc[1] = sn * a.y;
    }

    int s = g_rowptr[w], e = g_rowptr[w + 1];
    int j = s;
    for (; j + 4 <= e; j += 4) {
        int   si[4]; float ni[4];
#pragma unroll
        for (int u = 0; u < 4; u++) {
            si[u] = __ldg(&g_csr_src[j + u]);
            ni[u] = __ldg(&g_csr_nrm[j + u]);
        }
#pragma unroll
        for (int u = 0; u < 4; u++) {
            const float* p = X + (long)si[u] * C + lane * V;
            if constexpr (V == 4) {
                float4 a = *(const float4*)p;
                acc[0] = fmaf(ni[u], a.x, acc[0]); acc[1] = fmaf(ni[u], a.y, acc[1]);
                acc[2] = fmaf(ni[u], a.z, acc[2]); acc[3] = fmaf(ni[u], a.w, acc[3]);
            } else {
                float2 a = *(const float2*)p;
                acc[0] = fmaf(ni[u], a.x, acc[0]); acc[1] = fmaf(ni[u], a.y, acc[1]);
            }
        }
    }
    for (; j < e; j++) {
        int s0 = __ldg(&g_csr_src[j]);
        float n0 = __ldg(&g_csr_nrm[j]);
        const float* p0 = X + (long)s0 * C + lane * V;
        if constexpr (V == 4) {
            float4 a = *(const float4*)p0;
            acc[0] = fmaf(n0, a.x, acc[0]); acc[1] = fmaf(n0, a.y, acc[1]);
            acc[2] = fmaf(n0, a.z, acc[2]); acc[3] = fmaf(n0, a.w, acc[3]);
        } else {
            float2 a = *(const float2*)p0;
            acc[0] = fmaf(n0, a.x, acc[0]); acc[1] = fmaf(n0, a.y, acc[1]);
        }
    }

    float* yp = Y + (long)w * C + lane * V;
    if constexpr (V == 4) {
        *(float4*)yp = make_float4(acc[0], acc[1], acc[2], acc[3]);
    } else {
        *(float2*)yp = make_float2(acc[0], acc[1]);
    }
}

// ---------------- node GEMM (fused bias+relu) with FFMA2 ----------------
// 64 nodes/block, 256 threads; thread owns 4 nodes x 8 cols (as 4 f32x2 accs).
__global__ void gemm_node(const float* __restrict__ X, const float* __restrict__ W,
                          const float* __restrict__ B, float* __restrict__ Y,
                          int n, int K) {
    __shared__ float Xs[64 * 64];
    __shared__ float Ws[64 * 128];
    int tid = threadIdx.x;
    int cg = tid & 15;       // col group: cols cg*8 .. cg*8+7
    int ng = tid >> 4;       // node group: nodes ng*4 .. ng*4+3
    int n0 = blockIdx.x * 64;

    unsigned long long acc2[4][4];
#pragma unroll
    for (int j = 0; j < 4; j++)
#pragma unroll
        for (int q = 0; q < 4; q++) acc2[j][q] = 0ull;

    unsigned wsb = (unsigned)__cvta_generic_to_shared(Ws) + cg * 32;

    for (int kt = 0; kt < K; kt += 64) {
        for (int i = tid; i < 64 * 128; i += 256) Ws[i] = W[kt * 128 + i];
        for (int i = tid; i < 64 * 64; i += 256) {
            int nl = i >> 6, kk = i & 63;
            int node = n0 + nl;
            Xs[nl * 64 + kk] = (node < n) ? X[(long)node * K + kt + kk] : 0.f;
        }
        __syncthreads();
#pragma unroll 4
        for (int kk = 0; kk < 64; kk++) {
            unsigned long long w01, w23, w45, w67;
            lds_2x64(wsb + kk * 512,      w01, w23);
            lds_2x64(wsb + kk * 512 + 16, w45, w67);
#pragma unroll
            for (int j = 0; j < 4; j++) {
                float xv = Xs[(ng * 4 + j) * 64 + kk];
                unsigned long long xx = pack2(xv, xv);
                fma2(acc2[j][0], xx, w01);
                fma2(acc2[j][1], xx, w23);
                fma2(acc2[j][2], xx, w45);
                fma2(acc2[j][3], xx, w67);
            }
        }
        __syncthreads();
    }
    float4 ba = *(const float4*)&B[cg * 8];
    float4 bb = *(const float4*)&B[cg * 8 + 4];
#pragma unroll
    for (int j = 0; j < 4; j++) {
        int node = n0 + ng * 4 + j;
        if (node < n) {
            float2 p0 = unpack2(acc2[j][0]);
            float2 p1 = unpack2(acc2[j][1]);
            float2 p2 = unpack2(acc2[j][2]);
            float2 p3 = unpack2(acc2[j][3]);
            float4 a, b;
            a.x = fmaxf(p0.x + ba.x, 0.f);
            a.y = fmaxf(p0.y + ba.y, 0.f);
            a.z = fmaxf(p1.x + ba.z, 0.f);
            a.w = fmaxf(p1.y + ba.w, 0.f);
            b.x = fmaxf(p2.x + bb.x, 0.f);
            b.y = fmaxf(p2.y + bb.y, 0.f);
            b.z = fmaxf(p3.x + bb.z, 0.f);
            b.w = fmaxf(p3.y + bb.w, 0.f);
            *(float4*)&Y[(long)node * 128 + cg * 8]     = a;
            *(float4*)&Y[(long)node * 128 + cg * 8 + 4] = b;
        }
    }
}

// ---------------- pooling ----------------
__global__ void pool_kernel(const float4* __restrict__ h2, const int* __restrict__ batch) {
    unsigned gtid = blockIdx.x * blockDim.x + threadIdx.x;
    int n = gtid >> 5;
    if (n >= N_NODES) return;
    int lane = threadIdx.x & 31;
    int b = batch[n];
    float4 v = h2[n * 32 + lane];
    float* p = g_gsum + b * 128 + lane * 4;
    asm volatile("red.global.add.v4.f32 [%0], {%1,%2,%3,%4};"
                 :: "l"(p), "f"(v.x), "f"(v.y), "f"(v.z), "f"(v.w) : "memory");
    if (lane == 0) atomicAdd(&g_cnt[b], 1.f);
}

__global__ void cntinv_kernel() {
    int i = blockIdx.x * blockDim.x + threadIdx.x;
    if (i < N_GRAPHS) g_cntinv[i] = 1.f / fmaxf(g_cnt[i], 1.f);
}

// ---------------- per-cell-line regressor with FFMA2 (pack along k) ----------------
__global__ void regressor(const float* __restrict__ W1, const float* __restrict__ B1,
                          const float* __restrict__ W2, const float* __restrict__ B2,
                          const int* __restrict__ ddb, float* __restrict__ out) {
    int c = blockIdx.x;
    int tile = blockIdx.y;
    int cnt = g_clcnt[c];
    if (tile * 32 >= cnt) return;

    __shared__ float As[32 * 256];
    __shared__ int   sp[32], g0s[32], g1s[32];
    __shared__ float ci0[32], ci1[32];
    __shared__ float red[32][9];

    int tid = threadIdx.x;
    int base = g_offs[c] + tile * 32;
    if (tid < 32) {
        int valid = (tile * 32 + tid) < cnt;
        int p = valid ? g_sorted[base + tid] : -1;
        sp[tid] = p;
        int a = valid ? ddb[p] : 0;
        int b = valid ? ddb[N_PAIRS + p] : 0;
        g0s[tid] = a; g1s[tid] = b;
        ci0[tid] = g_cntinv[a]; ci1[tid] = g_cntinv[b];
    }
    __syncthreads();

    for (int i = tid; i < 32 * 256; i += 256) {
        int pi = i >> 8, e = i & 255;
        As[i] = (e < 128) ? g_gsum[g0s[pi] * 128 + e] * ci0[pi]
                          : g_gsum[g1s[pi] * 128 + (e - 128)] * ci1[pi];
    }
    __syncthreads();

    unsigned asb = (unsigned)__cvta_generic_to_shared(As);
    const float* w1 = W1 + c * (2 * EMB * HID) + tid;

    unsigned long long acc2[32];
#pragma unroll
    for (int i = 0; i < 32; i++) acc2[i] = 0ull;

    for (int k = 0; k < 256; k += 4) {
        float w0 = w1[(k + 0) * 256];
        float wA = w1[(k + 1) * 256];
        float wB = w1[(k + 2) * 256];
        float wC = w1[(k + 3) * 256];
        unsigned long long w01 = pack2(w0, wA);
        unsigned long long w23 = pack2(wB, wC);
        unsigned a = asb + k * 4;
#pragma unroll
        for (int i = 0; i < 32; i++) {
            unsigned long long a01, a23;
            lds_2x64(a + i * 1024, a01, a23);
            fma2(acc2[i], a01, w01);
            fma2(acc2[i], a23, w23);
        }
    }

    float b1t = B1[c * 256 + tid];
    float w2t = W2[c * 256 + tid];
    int warp = tid >> 5, lane = tid & 31;
#pragma unroll
    for (int i = 0; i < 32; i++) {
        float2 u = unpack2(acc2[i]);
        float h = fmaxf(u.x + u.y + b1t, 0.f);
        float v = h * w2t;
#pragma unroll
        for (int off = 16; off; off >>= 1)
            v += __shfl_down_sync(0xffffffffu, v, off);
        if (lane == 0) red[i][warp] = v;
    }
    __syncthreads();
    if (tid < 32) {
        int p = sp[tid];
        if (p >= 0) {
            float s = B2[c];
#pragma unroll
            for (int w = 0; w < 8; w++) s += red[tid][w];
            out[p] = s;
        }
    }
}

// ---------------- launch ----------------
extern "C" void kernel_launch(void* const* d_in, const int* in_sizes, int n_in,
                              void* d_out, int out_size) {
    const float* x        = (const float*)d_in[0];
    const float* conv1_w  = (const float*)d_in[1];
    const float* conv1_b  = (const float*)d_in[2];
    const float* conv2_w  = (const float*)d_in[3];
    const float* conv2_b  = (const float*)d_in[4];
    const float* reg_w1   = (const float*)d_in[5];
    const float* reg_b1   = (const float*)d_in[6];
    const float* reg_w2   = (const float*)d_in[7];
    const float* reg_b2   = (const float*)d_in[8];
    const int*   ei       = (const int*)d_in[9];
    const int*   batch    = (const int*)d_in[10];
    const int*   ddb      = (const int*)d_in[11];
    const int*   ecl      = (const int*)d_in[12];
    float* out = (float*)d_out;

    float* bufHW;  cudaGetSymbolAddress((void**)&bufHW, g_bufHW);
    float* bufAGG; cudaGetSymbolAddress((void**)&bufAGG, g_bufAGG);

    init_kernel<<<(N_GRAPHS * EMB + 255) / 256, 256>>>();
    degree_kernel<<<(N_EDGES + 255) / 256, 256>>>(ei);
    scanA<<<SCAN_BLOCKS, 256>>>();
    scanC<<<SCAN_BLOCKS, 256>>>();
    csr_scatter<<<(N_EDGES + 255) / 256, 256>>>(ei);

    cl_sort<<<1, 256>>>(ecl);

    // layer 1: aggregate x (64 ch) then transform
    agg_gather<IN_CH><<<(N_NODES * 32 + 255) / 256, 256>>>(x, bufAGG);
    gemm_node<<<(N_NODES + 63) / 64, 256>>>(bufAGG, conv1_w, conv1_b, bufHW, N_NODES, IN_CH);

    // layer 2
    agg_gather<EMB><<<(N_NODES * 32 + 255) / 256, 256>>>(bufHW, bufAGG);
    gemm_node<<<(N_NODES + 63) / 64, 256>>>(bufAGG, conv2_w, conv2_b, bufHW, N_NODES, EMB);

    // pooling
    pool_kernel<<<(N_NODES * 32 + 255) / 256, 256>>>((const float4*)bufHW, batch);
    cntinv_kernel<<<(N_GRAPHS + 255) / 256, 256>>>();

    // per-cell-line MLP head (64 tiles per line covers max bin count with margin)
    dim3 rg(N_CL, 64);
    regressor<<<rg, 256>>>(reg_w1, reg_b1, reg_w2, reg_b2, ddb, out);
}

// round 13
// speedup vs baseline: 1.0293x; 1.0293x over previous
#include <cuda_runtime.h>
#include <cuda_bf16.h>
#include <cstdint>

#define N_NODES  50000
#define N_EDGES  800000
#define N_GRAPHS 1024
#define N_PAIRS  16384
#define N_CL     16
#define IN_CH    64
#define EMB      128
#define HID      256

#define SCAN_BLOCKS ((N_NODES + 255) / 256)   // 196

// ---------------- scratch (device globals; no allocations) ----------------
__device__ float g_bufHW[N_NODES * EMB];
__device__ float g_bufAGG[N_NODES * EMB];
__device__ int   g_indeg[N_NODES];
__device__ float g_dinv[N_NODES];
__device__ int   g_rowptr[N_NODES + 1];
__device__ int   g_cursor2[N_NODES];
__device__ int   g_bsum[256];
__device__ int   g_csr_src[N_EDGES];
__device__ float g_csr_nrm[N_EDGES];
__device__ float g_gsum[N_GRAPHS * EMB];
__device__ float g_cnt[N_GRAPHS];
__device__ float g_cntinv[N_GRAPHS];
__device__ int   g_clcnt[N_CL];
__device__ int   g_offs[N_CL + 1];
__device__ int   g_sorted[N_PAIRS];

// ---------------- init ----------------
__global__ void init_kernel() {
    int i = blockIdx.x * blockDim.x + threadIdx.x;
    if (i < N_GRAPHS * EMB) g_gsum[i] = 0.f;
    if (i < N_NODES)  g_indeg[i] = 0;
    if (i < N_GRAPHS) g_cnt[i] = 0.f;
}

// ---------------- degree ----------------
__global__ void degree_kernel(const int* __restrict__ ei) {
    int e = blockIdx.x * blockDim.x + threadIdx.x;
    if (e < N_EDGES) atomicAdd(&g_indeg[ei[N_EDGES + e]], 1);  // target = col
}

// ---------------- CSR build ----------------
__global__ void scanA() {
    __shared__ int s[256];
    int t = threadIdx.x;
    int i = blockIdx.x * 256 + t;
    int v = (i < N_NODES) ? g_indeg[i] : 0;
    s[t] = v; __syncthreads();
#pragma unroll
    for (int off = 1; off < 256; off <<= 1) {
        int x = (t >= off) ? s[t - off] : 0;
        __syncthreads();
        s[t] += x;
        __syncthreads();
    }
    if (i < N_NODES) {
        g_rowptr[i] = s[t] - v;              // block-local exclusive
        g_dinv[i] = rsqrtf((float)(v + 1));  // +1 self-loop
    }
    if (t == 255) g_bsum[blockIdx.x] = s[255];
}

// fused: each block computes its own prefix over g_bsum, applies, writes cursor
__global__ void scanC() {
    __shared__ int warpsum[8];
    __shared__ int boff;
    int t = threadIdx.x, b = blockIdx.x;
    int v = 0;
    for (int j = t; j < b; j += 256) v += g_bsum[j];
#pragma unroll
    for (int off = 16; off; off >>= 1) v += __shfl_down_sync(0xffffffffu, v, off);
    if ((t & 31) == 0) warpsum[t >> 5] = v;
    __syncthreads();
    if (t == 0) {
        int s = 0;
#pragma unroll
        for (int w = 0; w < 8; w++) s += warpsum[w];
        boff = s;
    }
    __syncthreads();
    int i = b * 256 + t;
    if (i < N_NODES) {
        int r = g_rowptr[i] + boff;
        g_rowptr[i] = r;
        g_cursor2[i] = r;
    }
    if (i == 0) g_rowptr[N_NODES] = N_EDGES;
}

__global__ void csr_scatter(const int* __restrict__ ei) {
    int e = blockIdx.x * blockDim.x + threadIdx.x;
    if (e >= N_EDGES) return;
    int r = ei[e];
    int c = ei[N_EDGES + e];
    int pos = atomicAdd(&g_cursor2[c], 1);
    g_csr_src[pos] = r;
    g_csr_nrm[pos] = g_dinv[r] * g_dinv[c];
}

// ---------------- fused pair counting sort (single block) ----------------
__global__ void cl_sort(const int* __restrict__ ecl) {
    __shared__ int hist[N_CL], offs[N_CL], cur[N_CL];
    int tid = threadIdx.x, lane = tid & 31;
    if (tid < N_CL) hist[tid] = 0;
    __syncthreads();
    for (int p = tid; p < N_PAIRS; p += 256) {
        int c = ecl[p];
        unsigned m = __match_any_sync(0xffffffffu, c);
        if (lane == (__ffs(m) - 1)) atomicAdd(&hist[c], __popc(m));
    }
    __syncthreads();
    if (tid == 0) {
        int s = 0;
        for (int c = 0; c < N_CL; c++) { offs[c] = s; cur[c] = s; s += hist[c]; }
    }
    __syncthreads();
    for (int p = tid; p < N_PAIRS; p += 256) {
        int c = ecl[p];
        unsigned m = __match_any_sync(0xffffffffu, c);
        int leader = __ffs(m) - 1;
        int base;
        if (lane == leader) base = atomicAdd(&cur[c], __popc(m));
        base = __shfl_sync(0xffffffffu, base, leader);
        int rank = __popc(m & ((1u << lane) - 1));
        g_sorted[base + rank] = p;
    }
    if (tid < N_CL) { g_clcnt[tid] = hist[tid]; g_offs[tid] = offs[tid]; }
    if (tid == 0) g_offs[N_CL] = N_PAIRS;
}

// ---------------- CSR gather aggregation, unroll 4 ----------------
template <int C>
__global__ void agg_gather(const float* __restrict__ X, float* __restrict__ Y) {
    int w = (blockIdx.x * blockDim.x + threadIdx.x) >> 5;
    if (w >= N_NODES) return;
    int lane = threadIdx.x & 31;
    constexpr int V = C / 32;

    float d = g_dinv[w];
    float sn = d * d;
    float acc[V];
    const float* xp = X + (long)w * C + lane * V;
    if constexpr (V == 4) {
        float4 a = *(const float4*)xp;
        acc[0] = sn * a.x; acc[1] = sn * a.y; acc[2] = sn * a.z; acc[3] = sn * a.w;
    } else {
        float2 a = *(const float2*)xp;
        acc[0] = sn * a.x; acc[1] = sn * a.y;
    }

    int s = g_rowptr[w], e = g_rowptr[w + 1];
    int j = s;
    for (; j + 4 <= e; j += 4) {
        int   si[4]; float ni[4];
#pragma unroll
        for (int u = 0; u < 4; u++) {
            si[u] = __ldg(&g_csr_src[j + u]);
            ni[u] = __ldg(&g_csr_nrm[j + u]);
        }
#pragma unroll
        for (int u = 0; u < 4; u++) {
            const float* p = X + (long)si[u] * C + lane * V;
            if constexpr (V == 4) {
                float4 a = *(const float4*)p;
                acc[0] = fmaf(ni[u], a.x, acc[0]); acc[1] = fmaf(ni[u], a.y, acc[1]);
                acc[2] = fmaf(ni[u], a.z, acc[2]); acc[3] = fmaf(ni[u], a.w, acc[3]);
            } else {
                float2 a = *(const float2*)p;
                acc[0] = fmaf(ni[u], a.x, acc[0]); acc[1] = fmaf(ni[u], a.y, acc[1]);
            }
        }
    }
    for (; j < e; j++) {
        int s0 = __ldg(&g_csr_src[j]);
        float n0 = __ldg(&g_csr_nrm[j]);
        const float* p0 = X + (long)s0 * C + lane * V;
        if constexpr (V == 4) {
            float4 a = *(const float4*)p0;
            acc[0] = fmaf(n0, a.x, acc[0]); acc[1] = fmaf(n0, a.y, acc[1]);
            acc[2] = fmaf(n0, a.z, acc[2]); acc[3] = fmaf(n0, a.w, acc[3]);
        } else {
            float2 a = *(const float2*)p0;
            acc[0] = fmaf(n0, a.x, acc[0]); acc[1] = fmaf(n0, a.y, acc[1]);
        }
    }

    float* yp = Y + (long)w * C + lane * V;
    if constexpr (V == 4) {
        *(float4*)yp = make_float4(acc[0], acc[1], acc[2], acc[3]);
    } else {
        *(float2*)yp = make_float2(acc[0], acc[1]);
    }
}

// ---------------- node GEMM with fused bias+relu (scalar FMA — R1 version) ----------------
// 64 nodes per block, 256 threads, thread owns 4 nodes x 8 cols.
__global__ void gemm_node(const float* __restrict__ X, const float* __restrict__ W,
                          const float* __restrict__ B, float* __restrict__ Y,
                          int n, int K) {
    __shared__ float Xs[64 * 64];
    __shared__ float Ws[64 * 128];
    int tid = threadIdx.x;
    int cg = tid & 15;       // col group: cols cg*8 .. cg*8+7
    int ng = tid >> 4;       // node group: nodes ng*4 .. ng*4+3
    int n0 = blockIdx.x * 64;

    float acc[4][8];
#pragma unroll
    for (int j = 0; j < 4; j++)
#pragma unroll
        for (int q = 0; q < 8; q++) acc[j][q] = 0.f;

    for (int kt = 0; kt < K; kt += 64) {
        for (int i = tid; i < 64 * 128; i += 256) Ws[i] = W[kt * 128 + i];
        for (int i = tid; i < 64 * 64; i += 256) {
            int nl = i >> 6, kk = i & 63;
            int node = n0 + nl;
            Xs[nl * 64 + kk] = (node < n) ? X[(long)node * K + kt + kk] : 0.f;
        }
        __syncthreads();
#pragma unroll 8
        for (int kk = 0; kk < 64; kk++) {
            float4 wa = *(const float4*)&Ws[kk * 128 + cg * 8];
            float4 wb = *(const float4*)&Ws[kk * 128 + cg * 8 + 4];
#pragma unroll
            for (int j = 0; j < 4; j++) {
                float xv = Xs[(ng * 4 + j) * 64 + kk];
                acc[j][0] = fmaf(xv, wa.x, acc[j][0]);
                acc[j][1] = fmaf(xv, wa.y, acc[j][1]);
                acc[j][2] = fmaf(xv, wa.z, acc[j][2]);
                acc[j][3] = fmaf(xv, wa.w, acc[j][3]);
                acc[j][4] = fmaf(xv, wb.x, acc[j][4]);
                acc[j][5] = fmaf(xv, wb.y, acc[j][5]);
                acc[j][6] = fmaf(xv, wb.z, acc[j][6]);
                acc[j][7] = fmaf(xv, wb.w, acc[j][7]);
            }
        }
        __syncthreads();
    }
    float4 ba = *(const float4*)&B[cg * 8];
    float4 bb = *(const float4*)&B[cg * 8 + 4];
#pragma unroll
    for (int j = 0; j < 4; j++) {
        int node = n0 + ng * 4 + j;
        if (node < n) {
            float4 a, b;
            a.x = fmaxf(acc[j][0] + ba.x, 0.f);
            a.y = fmaxf(acc[j][1] + ba.y, 0.f);
            a.z = fmaxf(acc[j][2] + ba.z, 0.f);
            a.w = fmaxf(acc[j][3] + ba.w, 0.f);
            b.x = fmaxf(acc[j][4] + bb.x, 0.f);
            b.y = fmaxf(acc[j][5] + bb.y, 0.f);
            b.z = fmaxf(acc[j][6] + bb.z, 0.f);
            b.w = fmaxf(acc[j][7] + bb.w, 0.f);
            *(float4*)&Y[(long)node * 128 + cg * 8]     = a;
            *(float4*)&Y[(long)node * 128 + cg * 8 + 4] = b;
        }
    }
}

// ---------------- pooling ----------------
__global__ void pool_kernel(const float4* __restrict__ h2, const int* __restrict__ batch) {
    unsigned gtid = blockIdx.x * blockDim.x + threadIdx.x;
    int n = gtid >> 5;
    if (n >= N_NODES) return;
    int lane = threadIdx.x & 31;
    int b = batch[n];
    float4 v = h2[n * 32 + lane];
    float* p = g_gsum + b * 128 + lane * 4;
    asm volatile("red.global.add.v4.f32 [%0], {%1,%2,%3,%4};"
                 :: "l"(p), "f"(v.x), "f"(v.y), "f"(v.z), "f"(v.w) : "memory");
    if (lane == 0) atomicAdd(&g_cnt[b], 1.f);
}

__global__ void cntinv_kernel() {
    int i = blockIdx.x * blockDim.x + threadIdx.x;
    if (i < N_GRAPHS) g_cntinv[i] = 1.f / fmaxf(g_cnt[i], 1.f);
}

// ---------------- per-cell-line regressor (scalar FMA — R1 version + cntinv fold) --------
__global__ void regressor(const float* __restrict__ W1, const float* __restrict__ B1,
                          const float* __restrict__ W2, const float* __restrict__ B2,
                          const int* __restrict__ ddb, float* __restrict__ out) {
    int c = blockIdx.x;
    int tile = blockIdx.y;
    int cnt = g_clcnt[c];
    if (tile * 32 >= cnt) return;

    __shared__ float As[32 * 256];
    __shared__ int   sp[32], g0s[32], g1s[32];
    __shared__ float ci0[32], ci1[32];
    __shared__ float red[32][9];

    int tid = threadIdx.x;
    int base = g_offs[c] + tile * 32;
    if (tid < 32) {
        int valid = (tile * 32 + tid) < cnt;
        int p = valid ? g_sorted[base + tid] : -1;
        sp[tid] = p;
        int a = valid ? ddb[p] : 0;
        int b = valid ? ddb[N_PAIRS + p] : 0;
        g0s[tid] = a; g1s[tid] = b;
        ci0[tid] = g_cntinv[a]; ci1[tid] = g_cntinv[b];
    }
    __syncthreads();

    for (int i = tid; i < 32 * 256; i += 256) {
        int pi = i >> 8, e = i & 255;
        As[i] = (e < 128) ? g_gsum[g0s[pi] * 128 + e] * ci0[pi]
                          : g_gsum[g1s[pi] * 128 + (e - 128)] * ci1[pi];
    }
    __syncthreads();

    const float* w1 = W1 + c * (2 * EMB * HID) + tid;
    float acc[32];
#pragma unroll
    for (int i = 0; i < 32; i++) acc[i] = 0.f;

    for (int k = 0; k < 256; k += 4) {
        float w0 = w1[(k + 0) * 256];
        float wA = w1[(k + 1) * 256];
        float wB = w1[(k + 2) * 256];
        float wC = w1[(k + 3) * 256];
#pragma unroll
        for (int i = 0; i < 32; i++) {
            float4 a = *(const float4*)&As[i * 256 + k];
            float t = acc[i];
            t = fmaf(a.x, w0, t);
            t = fmaf(a.y, wA, t);
            t = fmaf(a.z, wB, t);
            t = fmaf(a.w, wC, t);
            acc[i] = t;
        }
    }

    float b1t = B1[c * 256 + tid];
    float w2t = W2[c * 256 + tid];
    int warp = tid >> 5, lane = tid & 31;
#pragma unroll
    for (int i = 0; i < 32; i++) {
        float h = fmaxf(acc[i] + b1t, 0.f);
        float v = h * w2t;
#pragma unroll
        for (int off = 16; off; off >>= 1)
            v += __shfl_down_sync(0xffffffffu, v, off);
        if (lane == 0) red[i][warp] = v;
    }
    __syncthreads();
    if (tid < 32) {
        int p = sp[tid];
        if (p >= 0) {
            float s = B2[c];
#pragma unroll
            for (int w = 0; w < 8; w++) s += red[tid][w];
            out[p] = s;
        }
    }
}

// ---------------- launch ----------------
extern "C" void kernel_launch(void* const* d_in, const int* in_sizes, int n_in,
                              void* d_out, int out_size) {
    const float* x        = (const float*)d_in[0];
    const float* conv1_w  = (const float*)d_in[1];
    const float* conv1_b  = (const float*)d_in[2];
    const float* conv2_w  = (const float*)d_in[3];
    const float* conv2_b  = (const float*)d_in[4];
    const float* reg_w1   = (const float*)d_in[5];
    const float* reg_b1   = (const float*)d_in[6];
    const float* reg_w2   = (const float*)d_in[7];
    const float* reg_b2   = (const float*)d_in[8];
    const int*   ei       = (const int*)d_in[9];
    const int*   batch    = (const int*)d_in[10];
    const int*   ddb      = (const int*)d_in[11];
    const int*   ecl      = (const int*)d_in[12];
    float* out = (float*)d_out;

    float* bufHW;  cudaGetSymbolAddress((void**)&bufHW, g_bufHW);
    float* bufAGG; cudaGetSymbolAddress((void**)&bufAGG, g_bufAGG);

    init_kernel<<<(N_GRAPHS * EMB + 255) / 256, 256>>>();
    degree_kernel<<<(N_EDGES + 255) / 256, 256>>>(ei);
    scanA<<<SCAN_BLOCKS, 256>>>();
    scanC<<<SCAN_BLOCKS, 256>>>();
    csr_scatter<<<(N_EDGES + 255) / 256, 256>>>(ei);

    cl_sort<<<1, 256>>>(ecl);

    // layer 1: aggregate x (64 ch) then transform
    agg_gather<IN_CH><<<(N_NODES * 32 + 255) / 256, 256>>>(x, bufAGG);
    gemm_node<<<(N_NODES + 63) / 64, 256>>>(bufAGG, conv1_w, conv1_b, bufHW, N_NODES, IN_CH);

    // layer 2
    agg_gather<EMB><<<(N_NODES * 32 + 255) / 256, 256>>>(bufHW, bufAGG);
    gemm_node<<<(N_NODES + 63) / 64, 256>>>(bufAGG, conv2_w, conv2_b, bufHW, N_NODES, EMB);

    // pooling
    pool_kernel<<<(N_NODES * 32 + 255) / 256, 256>>>((const float4*)bufHW, batch);
    cntinv_kernel<<<(N_GRAPHS + 255) / 256, 256>>>();

    // per-cell-line MLP head (64 tiles per line covers max bin count with margin)
    dim3 rg(N_CL, 64);
    regressor<<<rg, 256>>>(reg_w1, reg_b1, reg_w2, reg_b2, ddb, out);
}